// round 10
// baseline (speedup 1.0000x reference)
#include <cuda_runtime.h>
#include <cstdint>

// Problem constants: B=64, MEL_MAX=2000, TEXT_MAX=256, g=0.2
#define BATCH   64
#define MEL_MAX 2000
#define TXT_MAX 256
#define A_COEF  12.5f            // 1/(2 g^2)

#define SLABS   16               // t-slabs per batch
#define SLAB    125              // rows per slab (16*125 = 2000)
#define NBLK    (SLABS * BATCH)  // 1024 blocks
#define NTHR    256              // 8 warps; warp strides t by 8 within slab

typedef unsigned long long u64;

// Scratch (__device__ globals — no allocation allowed)
__device__ double       g_block[NBLK];
__device__ unsigned int g_count = 0;

// ---- packed f32x2 helpers (Blackwell) ----
__device__ __forceinline__ u64 pk2(float lo, float hi) {
    u64 r; asm("mov.b64 %0,{%1,%2};" : "=l"(r) : "f"(lo), "f"(hi)); return r;
}
__device__ __forceinline__ void unpk2(u64 a, float& lo, float& hi) {
    asm("mov.b64 {%0,%1},%2;" : "=f"(lo), "=f"(hi) : "l"(a));
}
__device__ __forceinline__ u64 mul2(u64 a, u64 b) {
    u64 r; asm("mul.rn.f32x2 %0,%1,%2;" : "=l"(r) : "l"(a), "l"(b)); return r;
}
__device__ __forceinline__ u64 add2(u64 a, u64 b) {
    u64 r; asm("add.rn.f32x2 %0,%1,%2;" : "=l"(r) : "l"(a), "l"(b)); return r;
}
__device__ __forceinline__ u64 fma2(u64 a, u64 b, u64 c) {
    u64 r; asm("fma.rn.f32x2 %0,%1,%2,%3;" : "=l"(r) : "l"(a), "l"(b), "l"(c)); return r;
}
// 16B streaming load (read-once data; evict-first)
__device__ __forceinline__ ulonglong2 ld16cs(const float* p) {
    ulonglong2 v;
    asm("ld.global.cs.v2.u64 {%0,%1},[%2];" : "=l"(v.x), "=l"(v.y) : "l"(p));
    return v;
}

// ---------------------------------------------------------------------------
// Fused kernel, slab-balanced, 4-row unrolled (8 LDG.128 in flight per warp).
// Block (x, b) owns t in [125x, min(125(x+1),ml)); warp w: t = 125x + w + 8k.
// Lane owns 8 contiguous text positions. Gaussian recurrent in both axes
// (no MUFU in the loop). Last block (atomic ticket) finalizes.
// ---------------------------------------------------------------------------
__global__ __launch_bounds__(NTHR) void fused_kernel(
    const float* __restrict__ pred,
    const int*   __restrict__ tlen,
    const int*   __restrict__ mlen,
    float*       __restrict__ out)
{
    const int lane = threadIdx.x & 31;
    const int wid  = threadIdx.x >> 5;
    const int b    = blockIdx.y;
    const int x    = blockIdx.x;

    const int ml    = __ldg(&mlen[b]);
    const int tbase = x * SLAB;

    u64 sP = 0, sE = 0;   // packed accumulators: sum p, sum E*p

    if (tbase < ml) {
        const int tl   = __ldg(&tlen[b]);
        const int tend = (tbase + SLAB < ml) ? tbase + SLAB : ml;

        // ---- loop-invariant constants ----
        const float inv_tl = 1.0f / (float)tl;
        const float inv_ml = 1.0f / (float)ml;
        const int   n0     = lane * 8;
        const float alpha0 = (float)n0 * inv_tl;
        const float ca     = 2.0f * A_COEF * inv_tl * inv_ml;
        const float cb     = -A_COEF * inv_tl * inv_tl * (float)(2 * n0 + 1);
        const float q2     = __expf(-2.0f * A_COEF * inv_tl * inv_tl);
        const float q2sq   = q2 * q2;
        const float q8     = q2sq * q2sq;
        const u64   Q4     = pk2(q8, q8);

        int count = tl - n0; if (count < 0) count = 0; if (count > 8) count = 8;
        const bool pred_lo = (count > 0);
        const bool pred_hi = (count > 4);
        const u64 mk0 = pk2(count > 0 ? 1.0f : 0.0f, count > 1 ? 1.0f : 0.0f);
        const u64 mk1 = pk2(count > 2 ? 1.0f : 0.0f, count > 3 ? 1.0f : 0.0f);
        const u64 mk2 = pk2(count > 4 ? 1.0f : 0.0f, count > 5 ? 1.0f : 0.0f);
        const u64 mk3 = pk2(count > 6 ? 1.0f : 0.0f, count > 7 ? 1.0f : 0.0f);

        // ---- t-direction seed recurrence (stride 8) ----
        const int   t0  = tbase + wid;
        const float di  = 8.0f * inv_ml;
        const float u0v = alpha0 - (float)t0 * inv_ml;
        float S  = __expf(-2.0f * A_COEF * di * di);
        float E0 = __expf(-A_COEF * u0v * u0v);
        float rr = __expf(2.0f * A_COEF * di * u0v - A_COEF * di * di);
        float m0 = __expf(fmaf(ca, (float)t0, cb));
        float RM = __expf(8.0f * ca);
        if (!pred_lo) { E0 = 0.0f; rr = 0.0f; m0 = 0.0f; RM = 0.0f; }

        // column chain for one row (packed even/odd recurrence)
        auto chain = [&](float E0v, float m0v, ulonglong2 lo, ulonglong2 hi) {
            const float ms = m0v * m0v;
            const float m2 = ms * q2;
            u64 E2 = pk2(E0v, E0v * m0v);
            u64 M2 = pk2(m2, m2 * q2sq);
            u64 mp;
            mp = mul2(lo.x, mk0); sP = add2(sP, mp); sE = fma2(E2, mp, sE);
            E2 = mul2(E2, M2); M2 = mul2(M2, Q4);
            mp = mul2(lo.y, mk1); sP = add2(sP, mp); sE = fma2(E2, mp, sE);
            E2 = mul2(E2, M2); M2 = mul2(M2, Q4);
            mp = mul2(hi.x, mk2); sP = add2(sP, mp); sE = fma2(E2, mp, sE);
            E2 = mul2(E2, M2);
            mp = mul2(hi.y, mk3); sP = add2(sP, mp); sE = fma2(E2, mp, sE);
        };

        const size_t rstep = (size_t)8 * TXT_MAX;
        const float* rowp = pred + (size_t)b * (MEL_MAX * TXT_MAX)
                                 + (size_t)t0 * TXT_MAX + n0;
        int t = t0;

        // ---- main loop: 4 rows (t, t+8, t+16, t+24), all loads front-batched ----
        for (; t + 24 < tend; t += 32, rowp += 4 * rstep) {
            ulonglong2 a0, b0, a1, b1, a2, b2, a3, b3;
            a0.x=0;a0.y=0; b0.x=0;b0.y=0; a1.x=0;a1.y=0; b1.x=0;b1.y=0;
            a2.x=0;a2.y=0; b2.x=0;b2.y=0; a3.x=0;a3.y=0; b3.x=0;b3.y=0;
            const float* r1 = rowp + rstep;
            const float* r2 = rowp + 2 * rstep;
            const float* r3 = rowp + 3 * rstep;
            if (pred_lo) {
                a0 = ld16cs(rowp); a1 = ld16cs(r1);
                a2 = ld16cs(r2);   a3 = ld16cs(r3);
            }
            if (pred_hi) {
                b0 = ld16cs(rowp + 4); b1 = ld16cs(r1 + 4);
                b2 = ld16cs(r2 + 4);   b3 = ld16cs(r3 + 4);
            }

            const float E0a = E0, m0a = m0; E0 *= rr; rr *= S; m0 *= RM;
            const float E0b = E0, m0b = m0; E0 *= rr; rr *= S; m0 *= RM;
            const float E0c = E0, m0c = m0; E0 *= rr; rr *= S; m0 *= RM;
            const float E0d = E0, m0d = m0; E0 *= rr; rr *= S; m0 *= RM;

            chain(E0a, m0a, a0, b0);
            chain(E0b, m0b, a1, b1);
            chain(E0c, m0c, a2, b2);
            chain(E0d, m0d, a3, b3);
        }

        // ---- tail: up to 3 single rows ----
        for (; t < tend; t += 8, rowp += rstep) {
            ulonglong2 a0, b0;
            a0.x=0;a0.y=0; b0.x=0;b0.y=0;
            if (pred_lo) a0 = ld16cs(rowp);
            if (pred_hi) b0 = ld16cs(rowp + 4);
            chain(E0, m0, a0, b0);
            E0 *= rr; rr *= S; m0 *= RM;
        }
    }

    // ---- combine: loss = sum p - sum E p ----
    float x0, x1, y0, y1;
    unpk2(sP, x0, x1);
    unpk2(sE, y0, y1);
    float tot = (x0 + x1) - (y0 + y1);

    #pragma unroll
    for (int o = 16; o > 0; o >>= 1)
        tot += __shfl_xor_sync(0xFFFFFFFFu, tot, o);

    __shared__ double wsum[8];
    if (lane == 0) wsum[wid] = (double)tot;
    __syncthreads();

    __shared__ bool amLast;
    const int bid = blockIdx.y * SLABS + blockIdx.x;
    if (threadIdx.x == 0) {
        double sacc = 0.0;
        #pragma unroll
        for (int k = 0; k < 8; k++) sacc += wsum[k];
        g_block[bid] = sacc;
        __threadfence();
        amLast = (atomicAdd(&g_count, 1u) == NBLK - 1);
    }
    __syncthreads();

    // ---- last block: final reduction + normalizer ----
    if (amLast) {
        __threadfence();
        double sv = 0.0;
        for (int k = threadIdx.x; k < NBLK; k += NTHR)
            sv += __ldcg(&g_block[k]);
        double sa = 0.0;
        if (threadIdx.x < BATCH)
            sa = (double)__ldg(&tlen[threadIdx.x]) * (double)__ldg(&mlen[threadIdx.x]);

        #pragma unroll
        for (int o = 16; o > 0; o >>= 1) {
            sv += __shfl_xor_sync(0xFFFFFFFFu, sv, o);
            sa += __shfl_xor_sync(0xFFFFFFFFu, sa, o);
        }

        __shared__ double fv[8], fa[8];
        if (lane == 0) { fv[wid] = sv; fa[wid] = sa; }
        __syncthreads();

        if (threadIdx.x == 0) {
            double tv = 0.0, ta = 0.0;
            #pragma unroll
            for (int k = 0; k < 8; k++) { tv += fv[k]; ta += fa[k]; }
            out[0] = (float)(tv / ta);   // attention_weight = 1.0
            g_count = 0;                 // reset for next graph replay
        }
    }
}

// ---------------------------------------------------------------------------
// Inputs (metadata order): targets (unused), predictions, text_lengths,
// mel_lengths. Output: single float.
// ---------------------------------------------------------------------------
extern "C" void kernel_launch(void* const* d_in, const int* in_sizes, int n_in,
                              void* d_out, int out_size)
{
    (void)in_sizes; (void)n_in; (void)out_size;
    const float* pred = (const float*)d_in[1];
    const int*   tlen = (const int*)d_in[2];
    const int*   mlen = (const int*)d_in[3];
    float*       out  = (float*)d_out;

    dim3 grid(SLABS, BATCH);
    fused_kernel<<<grid, NTHR>>>(pred, tlen, mlen, out);
}

// round 11
// speedup vs baseline: 1.1385x; 1.1385x over previous
#include <cuda_runtime.h>
#include <cstdint>

// Problem constants: B=64, MEL_MAX=2000, TEXT_MAX=256, g=0.2
#define BATCH   64
#define MEL_MAX 2000
#define TXT_MAX 256
#define A_COEF  12.5f            // 1/(2 g^2)

#define SLABS   16               // t-slabs per batch
#define SLAB    125              // rows per slab (16*125 = 2000)
#define NBLK    (SLABS * BATCH)  // 1024 blocks
#define NTHR    256              // 8 warps; warp strides t by 8 within slab

typedef unsigned long long u64;

// Scratch (__device__ globals — no allocation allowed)
__device__ double       g_block[NBLK];
__device__ unsigned int g_count = 0;

// ---- packed f32x2 helpers (Blackwell) ----
__device__ __forceinline__ u64 pk2(float lo, float hi) {
    u64 r; asm("mov.b64 %0,{%1,%2};" : "=l"(r) : "f"(lo), "f"(hi)); return r;
}
__device__ __forceinline__ void unpk2(u64 a, float& lo, float& hi) {
    asm("mov.b64 {%0,%1},%2;" : "=f"(lo), "=f"(hi) : "l"(a));
}
__device__ __forceinline__ u64 mul2(u64 a, u64 b) {
    u64 r; asm("mul.rn.f32x2 %0,%1,%2;" : "=l"(r) : "l"(a), "l"(b)); return r;
}
__device__ __forceinline__ u64 add2(u64 a, u64 b) {
    u64 r; asm("add.rn.f32x2 %0,%1,%2;" : "=l"(r) : "l"(a), "l"(b)); return r;
}
__device__ __forceinline__ u64 fma2(u64 a, u64 b, u64 c) {
    u64 r; asm("fma.rn.f32x2 %0,%1,%2,%3;" : "=l"(r) : "l"(a), "l"(b), "l"(c)); return r;
}

// ---------------------------------------------------------------------------
// Fused kernel, slab-balanced (identical structure to the 16.9us best kernel);
// the ONLY change this round: __launch_bounds__(256, 5) to cap registers at
// ~51 and raise residency from 4 to 5 blocks/SM (32 -> 40 warps).
// Block (x, b) owns t in [125x, min(125(x+1),ml)); warp w: t = 125x + w + 8k.
// Lane owns 8 contiguous text positions. Gaussian recurrent in both axes
// (no MUFU in the loop). Last block (atomic ticket) finalizes.
// ---------------------------------------------------------------------------
__global__ __launch_bounds__(NTHR, 5) void fused_kernel(
    const float* __restrict__ pred,
    const int*   __restrict__ tlen,
    const int*   __restrict__ mlen,
    float*       __restrict__ out)
{
    const int lane = threadIdx.x & 31;
    const int wid  = threadIdx.x >> 5;
    const int b    = blockIdx.y;
    const int x    = blockIdx.x;

    const int ml    = __ldg(&mlen[b]);
    const int tbase = x * SLAB;

    u64 sP = 0, sE = 0;   // packed accumulators: sum p, sum E*p

    if (tbase < ml) {
        const int tl   = __ldg(&tlen[b]);
        const int tend = (tbase + SLAB < ml) ? tbase + SLAB : ml;

        // ---- loop-invariant constants ----
        const float inv_tl = 1.0f / (float)tl;
        const float inv_ml = 1.0f / (float)ml;
        const int   n0     = lane * 8;
        const float alpha0 = (float)n0 * inv_tl;
        const float ca     = 2.0f * A_COEF * inv_tl * inv_ml;
        const float cb     = -A_COEF * inv_tl * inv_tl * (float)(2 * n0 + 1);
        const float q2     = __expf(-2.0f * A_COEF * inv_tl * inv_tl);
        const float q2sq   = q2 * q2;
        const float q8     = q2sq * q2sq;
        const u64   Q4     = pk2(q8, q8);

        int count = tl - n0; if (count < 0) count = 0; if (count > 8) count = 8;
        const bool pred_lo = (count > 0);
        const bool pred_hi = (count > 4);
        const u64 mk0 = pk2(count > 0 ? 1.0f : 0.0f, count > 1 ? 1.0f : 0.0f);
        const u64 mk1 = pk2(count > 2 ? 1.0f : 0.0f, count > 3 ? 1.0f : 0.0f);
        const u64 mk2 = pk2(count > 4 ? 1.0f : 0.0f, count > 5 ? 1.0f : 0.0f);
        const u64 mk3 = pk2(count > 6 ? 1.0f : 0.0f, count > 7 ? 1.0f : 0.0f);

        // ---- t-direction seed recurrence (stride 8) ----
        const int   t0  = tbase + wid;
        const float di  = 8.0f * inv_ml;
        const float u0v = alpha0 - (float)t0 * inv_ml;
        float S  = __expf(-2.0f * A_COEF * di * di);
        float E0 = __expf(-A_COEF * u0v * u0v);
        float rr = __expf(2.0f * A_COEF * di * u0v - A_COEF * di * di);
        float m0 = __expf(fmaf(ca, (float)t0, cb));
        float RM = __expf(8.0f * ca);
        if (!pred_lo) { E0 = 0.0f; rr = 0.0f; m0 = 0.0f; RM = 0.0f; }

        // column chain for one row (packed even/odd recurrence)
        auto chain = [&](float E0v, float m0v, ulonglong2 lo, ulonglong2 hi) {
            const float ms = m0v * m0v;
            const float m2 = ms * q2;
            u64 E2 = pk2(E0v, E0v * m0v);
            u64 M2 = pk2(m2, m2 * q2sq);
            u64 mp;
            mp = mul2(lo.x, mk0); sP = add2(sP, mp); sE = fma2(E2, mp, sE);
            E2 = mul2(E2, M2); M2 = mul2(M2, Q4);
            mp = mul2(lo.y, mk1); sP = add2(sP, mp); sE = fma2(E2, mp, sE);
            E2 = mul2(E2, M2); M2 = mul2(M2, Q4);
            mp = mul2(hi.x, mk2); sP = add2(sP, mp); sE = fma2(E2, mp, sE);
            E2 = mul2(E2, M2);
            mp = mul2(hi.y, mk3); sP = add2(sP, mp); sE = fma2(E2, mp, sE);
        };

        const float* rowp = pred + (size_t)b * (MEL_MAX * TXT_MAX)
                                 + (size_t)t0 * TXT_MAX + n0;
        int t = t0;

        // ---- main loop: rows t and t+8 per iteration ----
        for (; t + 8 < tend; t += 16, rowp += (size_t)16 * TXT_MAX) {
            ulonglong2 a0; a0.x = 0; a0.y = 0;
            ulonglong2 b0; b0.x = 0; b0.y = 0;
            ulonglong2 a1; a1.x = 0; a1.y = 0;
            ulonglong2 b1; b1.x = 0; b1.y = 0;
            const float* r1 = rowp + (size_t)8 * TXT_MAX;
            if (pred_lo) { a0 = *(const ulonglong2*)rowp;       a1 = *(const ulonglong2*)r1; }
            if (pred_hi) { b0 = *(const ulonglong2*)(rowp + 4); b1 = *(const ulonglong2*)(r1 + 4); }

            const float E0a = E0, m0a = m0;
            E0 *= rr; rr *= S; m0 *= RM;
            const float E0b = E0, m0b = m0;
            E0 *= rr; rr *= S; m0 *= RM;

            chain(E0a, m0a, a0, b0);
            chain(E0b, m0b, a1, b1);
        }

        // ---- tail: at most one row ----
        if (t < tend) {
            ulonglong2 a0; a0.x = 0; a0.y = 0;
            ulonglong2 b0; b0.x = 0; b0.y = 0;
            if (pred_lo) a0 = *(const ulonglong2*)rowp;
            if (pred_hi) b0 = *(const ulonglong2*)(rowp + 4);
            chain(E0, m0, a0, b0);
        }
    }

    // ---- combine: loss = sum p - sum E p ----
    float x0, x1, y0, y1;
    unpk2(sP, x0, x1);
    unpk2(sE, y0, y1);
    float tot = (x0 + x1) - (y0 + y1);

    #pragma unroll
    for (int o = 16; o > 0; o >>= 1)
        tot += __shfl_xor_sync(0xFFFFFFFFu, tot, o);

    __shared__ double wsum[8];
    if (lane == 0) wsum[wid] = (double)tot;
    __syncthreads();

    __shared__ bool amLast;
    const int bid = blockIdx.y * SLABS + blockIdx.x;
    if (threadIdx.x == 0) {
        double sacc = 0.0;
        #pragma unroll
        for (int k = 0; k < 8; k++) sacc += wsum[k];
        g_block[bid] = sacc;
        __threadfence();
        amLast = (atomicAdd(&g_count, 1u) == NBLK - 1);
    }
    __syncthreads();

    // ---- last block: final reduction + normalizer ----
    if (amLast) {
        __threadfence();
        double sv = 0.0;
        for (int k = threadIdx.x; k < NBLK; k += NTHR)
            sv += __ldcg(&g_block[k]);
        double sa = 0.0;
        if (threadIdx.x < BATCH)
            sa = (double)__ldg(&tlen[threadIdx.x]) * (double)__ldg(&mlen[threadIdx.x]);

        #pragma unroll
        for (int o = 16; o > 0; o >>= 1) {
            sv += __shfl_xor_sync(0xFFFFFFFFu, sv, o);
            sa += __shfl_xor_sync(0xFFFFFFFFu, sa, o);
        }

        __shared__ double fv[8], fa[8];
        if (lane == 0) { fv[wid] = sv; fa[wid] = sa; }
        __syncthreads();

        if (threadIdx.x == 0) {
            double tv = 0.0, ta = 0.0;
            #pragma unroll
            for (int k = 0; k < 8; k++) { tv += fv[k]; ta += fa[k]; }
            out[0] = (float)(tv / ta);   // attention_weight = 1.0
            g_count = 0;                 // reset for next graph replay
        }
    }
}

// ---------------------------------------------------------------------------
// Inputs (metadata order): targets (unused), predictions, text_lengths,
// mel_lengths. Output: single float.
// ---------------------------------------------------------------------------
extern "C" void kernel_launch(void* const* d_in, const int* in_sizes, int n_in,
                              void* d_out, int out_size)
{
    (void)in_sizes; (void)n_in; (void)out_size;
    const float* pred = (const float*)d_in[1];
    const int*   tlen = (const int*)d_in[2];
    const int*   mlen = (const int*)d_in[3];
    float*       out  = (float*)d_out;

    dim3 grid(SLABS, BATCH);
    fused_kernel<<<grid, NTHR>>>(pred, tlen, mlen, out);
}